// round 7
// baseline (speedup 1.0000x reference)
#include <cuda_runtime.h>
#include <cstdint>

// Problem constants
#define NB   64
#define NH   32
#define NW   32
#define ND   384
#define NBHW (NB*NH*NW)          // 65536 rows

// Scratch (device globals; no allocation allowed)
__device__ float g_Yhw[(size_t)NBHW * ND];      // Yh + Yw
__device__ float g_Wco[ND * ND];                // Wo @ Wc
__device__ float g_bias[ND];                    // Wo @ bc + bo

// ---------------------------------------------------------------------------
// Wco[o][d] = sum_k Wo[o][k] * Wc[k][d]
__global__ void wco_kernel(const float* __restrict__ Wo, const float* __restrict__ Wc) {
    __shared__ float As[16][16];
    __shared__ float Bs[16][17];
    int o = blockIdx.y * 16 + threadIdx.y;
    int d = blockIdx.x * 16 + threadIdx.x;
    float acc = 0.f;
    for (int k0 = 0; k0 < ND; k0 += 16) {
        As[threadIdx.y][threadIdx.x] = Wo[o * ND + k0 + threadIdx.x];
        Bs[threadIdx.y][threadIdx.x] = Wc[(k0 + threadIdx.y) * ND + d];
        __syncthreads();
#pragma unroll
        for (int k = 0; k < 16; k++) acc += As[threadIdx.y][k] * Bs[k][threadIdx.x];
        __syncthreads();
    }
    g_Wco[o * ND + d] = acc;
}

// bias[o] = bo[o] + sum_k Wo[o][k]*bc[k]
__global__ void bias_kernel(const float* __restrict__ Wo, const float* __restrict__ bc,
                            const float* __restrict__ bo) {
    int o = threadIdx.x;
    float s = bo[o];
    for (int k = 0; k < ND; k++) s += Wo[o * ND + k] * bc[k];
    g_bias[o] = s;
}

// ---------------------------------------------------------------------------
// Fully fused mixer pass: projection + grouped-mix logits + softmax + apply.
// which=0 (w-mix): block (b, h=s): rows j = w, x[b,s,j,:]; writes Yhw.
// which=1 (h-mix): block (b, w=s): rows j = h, x[b,j,s,:]; accumulates.
// smem: sX[32][388] | sW1[768] | sY[64] | sZ[1024] = 57,088 bytes dynamic.
#define MX_SX   0
#define MX_SW1  (32 * 388)
#define MX_SY   (MX_SW1 + 768)
#define MX_SZ   (MX_SY + 64)
#define MX_DYN  ((MX_SZ + 1024) * 4)

__global__ __launch_bounds__(384, 3) void mix_fused_kernel(
    const float* __restrict__ x, const float* __restrict__ W1,
    const float* __restrict__ b1, const float* __restrict__ W2,
    const float* __restrict__ b2, int which) {
    extern __shared__ float sm[];
    float* sX  = sm + MX_SX;
    float* sW1 = sm + MX_SW1;
    float* sY  = sm + MX_SY;
    float* sZ  = sm + MX_SZ;

    int tid = threadIdx.x;
    int blk = blockIdx.x;
    int b = blk >> 5, s = blk & 31;
    int warp = tid >> 5, lane = tid & 31;

    float* yb;
    size_t ostride;
    if (which) { yb = g_Yhw + ((size_t)b * 1024 + s) * ND + tid; ostride = (size_t)32 * ND; }
    else       { yb = g_Yhw + (size_t)blk * (32 * ND) + tid;     ostride = (size_t)ND; }

    // Stage W1 (2x384) and the 32 x-rows (each 384 floats) into smem.
    sW1[tid] = W1[tid];
    sW1[tid + 384] = W1[tid + 384];
    int rg = tid / 96, c4 = tid % 96;
#pragma unroll
    for (int it = 0; it < 8; it++) {
        int j = rg * 8 + it;
        int hh = which ? j : s;
        int ww = which ? s : j;
        const float4* src = (const float4*)(x + ((size_t)(b * 32 + hh) * 32 + ww) * ND);
        ((float4*)(sX + j * 388))[c4] = src[c4];
    }
    __syncthreads();

    // Projection: sY[e*32 + j] = dot(sX[j], W1[e]) + b1[e]
    for (int j = warp; j < 32; j += 12) {
        float p0 = 0.f, p1 = 0.f;
        const float* xr = sX + j * 388;
#pragma unroll
        for (int q = 0; q < 12; q++) {
            float xv = xr[lane + 32 * q];
            p0 += xv * sW1[lane + 32 * q];
            p1 += xv * sW1[384 + lane + 32 * q];
        }
#pragma unroll
        for (int off = 16; off; off >>= 1) {
            p0 += __shfl_xor_sync(~0u, p0, off);
            p1 += __shfl_xor_sync(~0u, p1, off);
        }
        if (lane == 0) { sY[j] = p0 + b1[0]; sY[32 + j] = p1 + b1[1]; }
    }
    __syncthreads();

    // Grouped-mix logits: sZ[t] for t = i*32+j
    for (int t = tid; t < 1024; t += 384) {
        int g = t >> 7;
        const float* yg = sY + g * 8;
        float4 w0 = *(const float4*)(W2 + t * 8);
        float4 w1 = *(const float4*)(W2 + t * 8 + 4);
        sZ[t] = b2[t]
            + yg[0] * w0.x + yg[1] * w0.y + yg[2] * w0.z + yg[3] * w0.w
            + yg[4] * w1.x + yg[5] * w1.y + yg[6] * w1.z + yg[7] * w1.w;
    }
    __syncthreads();

    // Row softmax (over j), in place.
    for (int i = warp; i < 32; i += 12) {
        float v = sZ[i * 32 + lane];
        float m = v;
#pragma unroll
        for (int off = 16; off; off >>= 1) m = fmaxf(m, __shfl_xor_sync(~0u, m, off));
        float e = __expf(v - m);
        float su = e;
#pragma unroll
        for (int off = 16; off; off >>= 1) su += __shfl_xor_sync(~0u, su, off);
        sZ[i * 32 + lane] = e * (1.0f / su);
    }
    __syncthreads();

    // Apply: out[i][d] = sum_j A[i][j] * sX[j][d]; thread = column d.
    // Two halves of 16 rows each to keep register count <= 56 (3 CTAs/SM).
    int d = tid;
#pragma unroll 1
    for (int half = 0; half < 2; half++) {
        float acc[16];
        if (which) {
#pragma unroll
            for (int i = 0; i < 16; i++) acc[i] = yb[(size_t)(half * 16 + i) * ostride];
        } else {
#pragma unroll
            for (int i = 0; i < 16; i++) acc[i] = 0.f;
        }
#pragma unroll 2
        for (int jb = 0; jb < 8; jb++) {
            float xv0 = sX[(jb * 4 + 0) * 388 + d];
            float xv1 = sX[(jb * 4 + 1) * 388 + d];
            float xv2 = sX[(jb * 4 + 2) * 388 + d];
            float xv3 = sX[(jb * 4 + 3) * 388 + d];
#pragma unroll
            for (int i = 0; i < 16; i++) {
                float4 a = *(const float4*)(sZ + (half * 16 + i) * 32 + jb * 4);
                acc[i] += a.x * xv0 + a.y * xv1 + a.z * xv2 + a.w * xv3;
            }
        }
#pragma unroll
        for (int i = 0; i < 16; i++) yb[(size_t)(half * 16 + i) * ostride] = acc[i];
    }
}

// ---------------------------------------------------------------------------
// Final fused GEMM via mma.sync fp16 (m16n8k16, fp32 accumulate).
// out[m,o] = sum_d Yhw[m,d]*Wo[o,d] + sum_d x[m,d]*Wco[o,d] + bias[o]
// CTA tile 128x128, warps 2(M)x4(N), warp tile 64x32, BK=16 (one k16 step),
// double buffer; fp32 staged via cp.async, converted to f16x2 at frag load.
#define SROW 20   // smem row stride in floats (80B)

static __device__ __forceinline__ uint32_t s2u(const void* p) {
    uint32_t a;
    asm("{ .reg .u64 t; cvta.to.shared.u64 t, %1; cvt.u32.u64 %0, t; }" : "=r"(a) : "l"(p));
    return a;
}
static __device__ __forceinline__ void cp16(uint32_t dst, const float* src) {
    asm volatile("cp.async.cg.shared.global [%0], [%1], 16;" :: "r"(dst), "l"(src));
}
// pack two fp32 -> f16x2 (lo = first/lower-k element)
static __device__ __forceinline__ uint32_t packh2(float2 v) {
    uint32_t r;
    asm("cvt.rn.f16x2.f32 %0, %1, %2;" : "=r"(r) : "f"(v.y), "f"(v.x));
    return r;
}
static __device__ __forceinline__ void mma16816(float* d, const uint32_t* a, const uint32_t* b) {
    asm volatile(
        "mma.sync.aligned.m16n8k16.row.col.f32.f16.f16.f32 "
        "{%0,%1,%2,%3},{%4,%5,%6,%7},{%8,%9},{%0,%1,%2,%3};"
        : "+f"(d[0]), "+f"(d[1]), "+f"(d[2]), "+f"(d[3])
        : "r"(a[0]), "r"(a[1]), "r"(a[2]), "r"(a[3]), "r"(b[0]), "r"(b[1]));
}

__global__ __launch_bounds__(256, 2) void gemm_mma_kernel(
    const float* __restrict__ x, const float* __restrict__ Wo, float* __restrict__ out) {
    __shared__ float sA[2][128 * SROW];
    __shared__ float sB[2][128 * SROW];

    int tid = threadIdx.x;
    int lane = tid & 31, warp = tid >> 5;
    int wm = warp >> 2, wn = warp & 3;       // warp coords: 2 x 4
    int g = lane >> 2, c = lane & 3;         // groupID, threadID_in_group
    int m0 = blockIdx.y * 128;
    int n0 = blockIdx.x * 128;

    float acc[4][4][4];
#pragma unroll
    for (int mi = 0; mi < 4; mi++)
#pragma unroll
        for (int ni = 0; ni < 4; ni++)
#pragma unroll
            for (int r = 0; r < 4; r++) acc[mi][ni][r] = 0.f;

    // chunk ch (0..47): K=768 over two phases
    auto load_chunk = [&](int ch, int buf) {
        const float* A; const float* B; int ko;
        if (ch < 24) { A = g_Yhw + (size_t)m0 * ND; B = Wo + (size_t)n0 * ND;    ko = ch * 16; }
        else         { A = x     + (size_t)m0 * ND; B = g_Wco + (size_t)n0 * ND; ko = ch * 16 - 384; }
        uint32_t ab = s2u(&sA[buf][0]);
        uint32_t bb = s2u(&sB[buf][0]);
#pragma unroll
        for (int q = 0; q < 2; q++) {
            int f = tid + q * 256;           // 512 float4 per matrix
            int row = f >> 2, kg = f & 3;
            cp16(ab + row * (SROW * 4) + kg * 16, A + (size_t)row * ND + ko + kg * 4);
            cp16(bb + row * (SROW * 4) + kg * 16, B + (size_t)row * ND + ko + kg * 4);
        }
        asm volatile("cp.async.commit_group;" ::: "memory");
    };

    load_chunk(0, 0);

#pragma unroll 1
    for (int i = 0; i < 48; i++) {
        int buf = i & 1;
        if (i + 1 < 48) load_chunk(i + 1, buf ^ 1);
        if (i + 1 < 48) asm volatile("cp.async.wait_group 1;" ::: "memory");
        else            asm volatile("cp.async.wait_group 0;" ::: "memory");
        __syncthreads();

        const float* pA = &sA[buf][0];
        const float* pB = &sB[buf][0];
        // One m16n8k16 step covers the whole BK=16 chunk.
        uint32_t afr[4][4];
#pragma unroll
        for (int mi = 0; mi < 4; mi++) {
            int r0 = (wm * 64 + mi * 16 + g) * SROW + 2 * c;
            afr[mi][0] = packh2(*(const float2*)(pA + r0));
            afr[mi][1] = packh2(*(const float2*)(pA + r0 + 8 * SROW));
            afr[mi][2] = packh2(*(const float2*)(pA + r0 + 8));
            afr[mi][3] = packh2(*(const float2*)(pA + r0 + 8 * SROW + 8));
        }
        uint32_t bfr[4][2];
#pragma unroll
        for (int ni = 0; ni < 4; ni++) {
            int r0 = (wn * 32 + ni * 8 + g) * SROW + 2 * c;
            bfr[ni][0] = packh2(*(const float2*)(pB + r0));
            bfr[ni][1] = packh2(*(const float2*)(pB + r0 + 8));
        }
#pragma unroll
        for (int mi = 0; mi < 4; mi++)
#pragma unroll
            for (int ni = 0; ni < 4; ni++)
                mma16816(acc[mi][ni], afr[mi], bfr[ni]);
        __syncthreads();
    }

    // Epilogue: D layout m16n8: c0/c1 at (g, 2c/2c+1), c2/c3 at (g+8, ...)
#pragma unroll
    for (int ni = 0; ni < 4; ni++) {
        int col = n0 + wn * 32 + ni * 8 + 2 * c;
        float b0 = g_bias[col], b1 = g_bias[col + 1];
#pragma unroll
        for (int mi = 0; mi < 4; mi++) {
            int row = m0 + wm * 64 + mi * 16 + g;
            float2 v0 = {acc[mi][ni][0] + b0, acc[mi][ni][1] + b1};
            float2 v1 = {acc[mi][ni][2] + b0, acc[mi][ni][3] + b1};
            *(float2*)(out + (size_t)row * ND + col) = v0;
            *(float2*)(out + (size_t)(row + 8) * ND + col) = v1;
        }
    }
}

// ---------------------------------------------------------------------------
extern "C" void kernel_launch(void* const* d_in, const int* in_sizes, int n_in,
                              void* d_out, int out_size) {
    const float* x   = (const float*)d_in[0];
    const float* Wc  = (const float*)d_in[1];
    const float* bc  = (const float*)d_in[2];
    const float* Wo  = (const float*)d_in[3];
    const float* bo  = (const float*)d_in[4];
    const float* W1h = (const float*)d_in[5];
    const float* b1h = (const float*)d_in[6];
    const float* W2h = (const float*)d_in[7];
    const float* b2h = (const float*)d_in[8];
    const float* W1w = (const float*)d_in[9];
    const float* b1w = (const float*)d_in[10];
    const float* W2w = (const float*)d_in[11];
    const float* b2w = (const float*)d_in[12];
    float* out = (float*)d_out;

    static int attr_set = 0;
    if (!attr_set) {
        cudaFuncSetAttribute(mix_fused_kernel, cudaFuncAttributeMaxDynamicSharedMemorySize, MX_DYN);
        attr_set = 1;
    }

    wco_kernel<<<dim3(24, 24), dim3(16, 16)>>>(Wo, Wc);
    bias_kernel<<<1, 384>>>(Wo, bc, bo);
    // which=0: w-mix (block (b,h)), writes Yhw
    mix_fused_kernel<<<NB * NH, 384, MX_DYN>>>(x, W1w, b1w, W2w, b2w, 0);
    // which=1: h-mix (block (b,w)), accumulates into Yhw
    mix_fused_kernel<<<NB * NW, 384, MX_DYN>>>(x, W1h, b1h, W2h, b2h, 1);
    gemm_mma_kernel<<<dim3(ND / 128, NBHW / 128), 256>>>(x, Wo, out);
}

// round 9
// speedup vs baseline: 1.1860x; 1.1860x over previous
#include <cuda_runtime.h>
#include <cstdint>

// Problem constants
#define NB   64
#define NH   32
#define NW   32
#define ND   384
#define NBHW (NB*NH*NW)          // 65536 rows

// Scratch (device globals; no allocation allowed)
__device__ float g_Yhw[(size_t)NBHW * ND];      // Yh + Yw
__device__ float g_Wco[ND * ND];                // Wo @ Wc
__device__ float g_bias[ND];                    // Wo @ bc + bo

static __device__ __forceinline__ uint32_t s2u(const void* p) {
    uint32_t a;
    asm("{ .reg .u64 t; cvta.to.shared.u64 t, %1; cvt.u32.u64 %0, t; }" : "=r"(a) : "l"(p));
    return a;
}
static __device__ __forceinline__ void cp16(uint32_t dst, const float* src) {
    asm volatile("cp.async.cg.shared.global [%0], [%1], 16;" :: "r"(dst), "l"(src));
}
static __device__ __forceinline__ uint32_t f2tf(float f) {
    uint32_t r;
    asm("cvt.rna.tf32.f32 %0, %1;" : "=r"(r) : "f"(f));
    return r;
}
static __device__ __forceinline__ void mma1688(float* d, const uint32_t* a, const uint32_t* b) {
    asm volatile(
        "mma.sync.aligned.m16n8k8.row.col.f32.tf32.tf32.f32 "
        "{%0,%1,%2,%3},{%4,%5,%6,%7},{%8,%9},{%0,%1,%2,%3};"
        : "+f"(d[0]), "+f"(d[1]), "+f"(d[2]), "+f"(d[3])
        : "r"(a[0]), "r"(a[1]), "r"(a[2]), "r"(a[3]), "r"(b[0]), "r"(b[1]));
}

// ---------------------------------------------------------------------------
// Wco[o][d] = sum_k Wo[o][k] * Wc[k][d]
__global__ void wco_kernel(const float* __restrict__ Wo, const float* __restrict__ Wc) {
    __shared__ float As[16][16];
    __shared__ float Bs[16][17];
    int o = blockIdx.y * 16 + threadIdx.y;
    int d = blockIdx.x * 16 + threadIdx.x;
    float acc = 0.f;
    for (int k0 = 0; k0 < ND; k0 += 16) {
        As[threadIdx.y][threadIdx.x] = Wo[o * ND + k0 + threadIdx.x];
        Bs[threadIdx.y][threadIdx.x] = Wc[(k0 + threadIdx.y) * ND + d];
        __syncthreads();
#pragma unroll
        for (int k = 0; k < 16; k++) acc += As[threadIdx.y][k] * Bs[k][threadIdx.x];
        __syncthreads();
    }
    g_Wco[o * ND + d] = acc;
}

// bias[o] = bo[o] + sum_k Wo[o][k]*bc[k]
__global__ void bias_kernel(const float* __restrict__ Wo, const float* __restrict__ bc,
                            const float* __restrict__ bo) {
    int o = threadIdx.x;
    float s = bo[o];
    for (int k = 0; k < ND; k++) s += Wo[o * ND + k] * bc[k];
    g_bias[o] = s;
}

// ---------------------------------------------------------------------------
// Fully fused mixer pass: projection + grouped-mix logits + softmax + tensor-core apply.
// which=0 (w-mix): block (b, h=s): rows j = w, x[b,s,j,:]; writes Yhw rows (b,s,i,:).
// which=1 (h-mix): block (b, w=s): rows j = h, x[b,j,s,:]; accumulates rows (b,i,s,:).
// smem floats: sX[32][388] | sW1[768] | sY[64] | sZ[32][36]
#define SXST  388
#define SZST  36
#define MX_SX   0
#define MX_SW1  (32 * SXST)
#define MX_SY   (MX_SW1 + 768)
#define MX_SZ   (MX_SY + 64)
#define MX_DYN  ((MX_SZ + 32 * SZST) * 4)   // 57,600 bytes

__global__ __launch_bounds__(384, 2) void mix_fused_kernel(
    const float* __restrict__ x, const float* __restrict__ W1,
    const float* __restrict__ b1, const float* __restrict__ W2,
    const float* __restrict__ b2, int which) {
    extern __shared__ float sm[];
    float* sX  = sm + MX_SX;
    float* sW1 = sm + MX_SW1;
    float* sY  = sm + MX_SY;
    float* sZ  = sm + MX_SZ;

    int tid = threadIdx.x;
    int blk = blockIdx.x;
    int b = blk >> 5, s = blk & 31;
    int warp = tid >> 5, lane = tid & 31;
    int g = lane >> 2, c = lane & 3;
    int dbase = warp * 32;                   // this warp's 32 output columns

    float* ybase;
    size_t ostride;
    if (which) { ybase = g_Yhw + ((size_t)b * 1024 + s) * ND; ostride = (size_t)32 * ND; }
    else       { ybase = g_Yhw + (size_t)blk * (32 * ND);     ostride = (size_t)ND; }

    // MMA accumulators; which=1 preloads its RMW values now (latency hidden
    // behind all the staging / proj / softmax below).
    float acc[2][4][4];
#pragma unroll
    for (int mi = 0; mi < 2; mi++)
#pragma unroll
        for (int ni = 0; ni < 4; ni++) {
            if (which) {
                int col = dbase + ni * 8 + 2 * c;
                float2 u0 = *(const float2*)(ybase + (size_t)(mi * 16 + g) * ostride + col);
                float2 u1 = *(const float2*)(ybase + (size_t)(mi * 16 + g + 8) * ostride + col);
                acc[mi][ni][0] = u0.x; acc[mi][ni][1] = u0.y;
                acc[mi][ni][2] = u1.x; acc[mi][ni][3] = u1.y;
            } else {
                acc[mi][ni][0] = acc[mi][ni][1] = acc[mi][ni][2] = acc[mi][ni][3] = 0.f;
            }
        }

    // Stage W1 (2x384) and the 32 x-rows (each 384 floats) into smem.
    sW1[tid] = W1[tid];
    sW1[tid + 384] = W1[tid + 384];
    int rg = tid / 96, c4 = tid % 96;
#pragma unroll
    for (int it = 0; it < 8; it++) {
        int j = rg * 8 + it;
        int hh = which ? j : s;
        int ww = which ? s : j;
        const float4* src = (const float4*)(x + ((size_t)(b * 32 + hh) * 32 + ww) * ND);
        ((float4*)(sX + j * SXST))[c4] = src[c4];
    }
    __syncthreads();

    // Projection: sY[e*32 + j] = dot(sX[j], W1[e]) + b1[e]
    for (int j = warp; j < 32; j += 12) {
        float p0 = 0.f, p1 = 0.f;
        const float* xr = sX + j * SXST;
#pragma unroll
        for (int q = 0; q < 12; q++) {
            float xv = xr[lane + 32 * q];
            p0 += xv * sW1[lane + 32 * q];
            p1 += xv * sW1[384 + lane + 32 * q];
        }
#pragma unroll
        for (int off = 16; off; off >>= 1) {
            p0 += __shfl_xor_sync(~0u, p0, off);
            p1 += __shfl_xor_sync(~0u, p1, off);
        }
        if (lane == 0) { sY[j] = p0 + b1[0]; sY[32 + j] = p1 + b1[1]; }
    }
    __syncthreads();

    // Grouped-mix logits: sZ[i][j] for t = i*32+j
    for (int t = tid; t < 1024; t += 384) {
        int i = t >> 5, j = t & 31;
        int grp = t >> 7;
        const float* yg = sY + grp * 8;
        float4 w0 = *(const float4*)(W2 + t * 8);
        float4 w1 = *(const float4*)(W2 + t * 8 + 4);
        sZ[i * SZST + j] = b2[t]
            + yg[0] * w0.x + yg[1] * w0.y + yg[2] * w0.z + yg[3] * w0.w
            + yg[4] * w1.x + yg[5] * w1.y + yg[6] * w1.z + yg[7] * w1.w;
    }
    __syncthreads();

    // Row softmax (over j), in place.
    for (int i = warp; i < 32; i += 12) {
        float v = sZ[i * SZST + lane];
        float m = v;
#pragma unroll
        for (int off = 16; off; off >>= 1) m = fmaxf(m, __shfl_xor_sync(~0u, m, off));
        float e = __expf(v - m);
        float su = e;
#pragma unroll
        for (int off = 16; off; off >>= 1) su += __shfl_xor_sync(~0u, su, off);
        sZ[i * SZST + lane] = e * (1.0f / su);
    }
    __syncthreads();

    // Tensor-core apply: Y[32,384] (+)= attn[32,32] @ X[32,384].
    // Warp = 32-column tile; mi in {0,1} m16 tiles; 4 k8 steps.
#pragma unroll
    for (int ks = 0; ks < 4; ks++) {
        int k0 = ks * 8;
        uint32_t a[2][4];
#pragma unroll
        for (int mi = 0; mi < 2; mi++) {
            int row = mi * 16 + g;
            a[mi][0] = f2tf(sZ[row * SZST + k0 + c]);
            a[mi][1] = f2tf(sZ[(row + 8) * SZST + k0 + c]);
            a[mi][2] = f2tf(sZ[row * SZST + k0 + c + 4]);
            a[mi][3] = f2tf(sZ[(row + 8) * SZST + k0 + c + 4]);
        }
        uint32_t bb[4][2];
#pragma unroll
        for (int ni = 0; ni < 4; ni++) {
            bb[ni][0] = f2tf(sX[(k0 + c) * SXST + dbase + ni * 8 + g]);
            bb[ni][1] = f2tf(sX[(k0 + c + 4) * SXST + dbase + ni * 8 + g]);
        }
#pragma unroll
        for (int mi = 0; mi < 2; mi++)
#pragma unroll
            for (int ni = 0; ni < 4; ni++)
                mma1688(acc[mi][ni], a[mi], bb[ni]);
    }

    // Epilogue: D[g][2c], D[g][2c+1] in c0/c1; rows +8 in c2/c3.
#pragma unroll
    for (int mi = 0; mi < 2; mi++)
#pragma unroll
        for (int ni = 0; ni < 4; ni++) {
            int col = dbase + ni * 8 + 2 * c;
            float2 v0 = {acc[mi][ni][0], acc[mi][ni][1]};
            float2 v1 = {acc[mi][ni][2], acc[mi][ni][3]};
            *(float2*)(ybase + (size_t)(mi * 16 + g) * ostride + col) = v0;
            *(float2*)(ybase + (size_t)(mi * 16 + g + 8) * ostride + col) = v1;
        }
}

// ---------------------------------------------------------------------------
// Final fused GEMM via mma.sync tf32 (R3/R6 configuration — known good).
// out[m,o] = sum_d Yhw[m,d]*Wo[o,d] + sum_d x[m,d]*Wco[o,d] + bias[o]
// CTA tile 128x128, warps 2(M)x4(N), warp tile 64x32, BK=16, double buffer.
#define SROW 20   // smem row stride in floats (80B): conflict-free frag access

__global__ __launch_bounds__(256, 2) void gemm_mma_kernel(
    const float* __restrict__ x, const float* __restrict__ Wo, float* __restrict__ out) {
    __shared__ float sA[2][128 * SROW];
    __shared__ float sB[2][128 * SROW];

    int tid = threadIdx.x;
    int lane = tid & 31, warp = tid >> 5;
    int wm = warp >> 2, wn = warp & 3;       // warp coords: 2 x 4
    int g = lane >> 2, c = lane & 3;         // groupID, threadID_in_group
    int m0 = blockIdx.y * 128;
    int n0 = blockIdx.x * 128;

    float acc[4][4][4];
#pragma unroll
    for (int mi = 0; mi < 4; mi++)
#pragma unroll
        for (int ni = 0; ni < 4; ni++)
#pragma unroll
            for (int r = 0; r < 4; r++) acc[mi][ni][r] = 0.f;

    // chunk ch (0..47): K=768 over two phases
    auto load_chunk = [&](int ch, int buf) {
        const float* A; const float* B; int ko;
        if (ch < 24) { A = g_Yhw + (size_t)m0 * ND; B = Wo + (size_t)n0 * ND;    ko = ch * 16; }
        else         { A = x     + (size_t)m0 * ND; B = g_Wco + (size_t)n0 * ND; ko = ch * 16 - 384; }
        uint32_t ab = s2u(&sA[buf][0]);
        uint32_t bb = s2u(&sB[buf][0]);
#pragma unroll
        for (int q = 0; q < 2; q++) {
            int f = tid + q * 256;           // 512 float4 per matrix
            int row = f >> 2, kg = f & 3;
            cp16(ab + row * (SROW * 4) + kg * 16, A + (size_t)row * ND + ko + kg * 4);
            cp16(bb + row * (SROW * 4) + kg * 16, B + (size_t)row * ND + ko + kg * 4);
        }
        asm volatile("cp.async.commit_group;" ::: "memory");
    };

    load_chunk(0, 0);

#pragma unroll 1
    for (int i = 0; i < 48; i++) {
        int buf = i & 1;
        if (i + 1 < 48) load_chunk(i + 1, buf ^ 1);
        if (i + 1 < 48) asm volatile("cp.async.wait_group 1;" ::: "memory");
        else            asm volatile("cp.async.wait_group 0;" ::: "memory");
        __syncthreads();

        const float* pA = &sA[buf][0];
        const float* pB = &sB[buf][0];
#pragma unroll
        for (int ks = 0; ks < 2; ks++) {
            int kb = ks * 8;
            uint32_t afr[4][4];
#pragma unroll
            for (int mi = 0; mi < 4; mi++) {
                int r0 = (wm * 64 + mi * 16 + g) * SROW + kb + c;
                afr[mi][0] = f2tf(pA[r0]);
                afr[mi][1] = f2tf(pA[r0 + 8 * SROW]);
                afr[mi][2] = f2tf(pA[r0 + 4]);
                afr[mi][3] = f2tf(pA[r0 + 8 * SROW + 4]);
            }
            uint32_t bfr[4][2];
#pragma unroll
            for (int ni = 0; ni < 4; ni++) {
                int r0 = (wn * 32 + ni * 8 + g) * SROW + kb + c;
                bfr[ni][0] = f2tf(pB[r0]);
                bfr[ni][1] = f2tf(pB[r0 + 4]);
            }
#pragma unroll
            for (int mi = 0; mi < 4; mi++)
#pragma unroll
                for (int ni = 0; ni < 4; ni++)
                    mma1688(acc[mi][ni], afr[mi], bfr[ni]);
        }
        __syncthreads();
    }

    // Epilogue
#pragma unroll
    for (int ni = 0; ni < 4; ni++) {
        int col = n0 + wn * 32 + ni * 8 + 2 * c;
        float b0 = g_bias[col], b1 = g_bias[col + 1];
#pragma unroll
        for (int mi = 0; mi < 4; mi++) {
            int row = m0 + wm * 64 + mi * 16 + g;
            float2 v0 = {acc[mi][ni][0] + b0, acc[mi][ni][1] + b1};
            float2 v1 = {acc[mi][ni][2] + b0, acc[mi][ni][3] + b1};
            *(float2*)(out + (size_t)row * ND + col) = v0;
            *(float2*)(out + (size_t)(row + 8) * ND + col) = v1;
        }
    }
}

// ---------------------------------------------------------------------------
extern "C" void kernel_launch(void* const* d_in, const int* in_sizes, int n_in,
                              void* d_out, int out_size) {
    const float* x   = (const float*)d_in[0];
    const float* Wc  = (const float*)d_in[1];
    const float* bc  = (const float*)d_in[2];
    const float* Wo  = (const float*)d_in[3];
    const float* bo  = (const float*)d_in[4];
    const float* W1h = (const float*)d_in[5];
    const float* b1h = (const float*)d_in[6];
    const float* W2h = (const float*)d_in[7];
    const float* b2h = (const float*)d_in[8];
    const float* W1w = (const float*)d_in[9];
    const float* b1w = (const float*)d_in[10];
    const float* W2w = (const float*)d_in[11];
    const float* b2w = (const float*)d_in[12];
    float* out = (float*)d_out;

    static int attr_set = 0;
    if (!attr_set) {
        cudaFuncSetAttribute(mix_fused_kernel, cudaFuncAttributeMaxDynamicSharedMemorySize, MX_DYN);
        attr_set = 1;
    }

    wco_kernel<<<dim3(24, 24), dim3(16, 16)>>>(Wo, Wc);
    bias_kernel<<<1, 384>>>(Wo, bc, bo);
    // which=0: w-mix (block (b,h)), writes Yhw
    mix_fused_kernel<<<NB * NH, 384, MX_DYN>>>(x, W1w, b1w, W2w, b2w, 0);
    // which=1: h-mix (block (b,w)), accumulates into Yhw
    mix_fused_kernel<<<NB * NW, 384, MX_DYN>>>(x, W1h, b1h, W2h, b2h, 1);
    gemm_mma_kernel<<<dim3(ND / 128, NBHW / 128), 256>>>(x, Wo, out);
}